// round 2
// baseline (speedup 1.0000x reference)
#include <cuda_runtime.h>
#include <cuda_bf16.h>
#include <cstdint>

// Problem constants (from reference)
#define N_NODES 50000
#define N_EDGES 800000
#define D_IN    128
#define D_HID   256
#define D_OUT   256

// ---------------------------------------------------------------------------
// Scratch (no allocation allowed -> __device__ globals)
// ---------------------------------------------------------------------------
__device__ float g_deg[N_NODES];
__device__ float g_agg1[(size_t)N_NODES * D_IN];    // 25.6 MB
__device__ float g_h[(size_t)N_NODES * D_HID];      // 51.2 MB
__device__ float g_agg2[(size_t)N_NODES * D_HID];   // 51.2 MB
__device__ int   g_is64;                            // edge index dtype flag

// ---------------------------------------------------------------------------
// Detect whether edge_index is int64 or int32.
// If the buffer is really int32, reading it as int64 fuses pairs
// (lo + hi*2^32); hi is a node id in [0, 50000) and is nonzero w.p. ~1-2e-5,
// so over 4096 samples an int32 buffer is flagged with near-certainty.
// A true int64 buffer always has every value in [0, N_NODES).
// ---------------------------------------------------------------------------
__global__ void detect_idx_kernel(const long long* __restrict__ p) {
    __shared__ int bad;
    if (threadIdx.x == 0) bad = 0;
    __syncthreads();
    for (int i = threadIdx.x; i < 4096; i += blockDim.x) {
        long long v = p[i];
        if (v < 0 || v >= N_NODES) bad = 1;
    }
    __syncthreads();
    if (threadIdx.x == 0) g_is64 = bad ? 0 : 1;
}

__device__ __forceinline__ int load_idx(const void* base, int i) {
    if (g_is64) return (int)((const long long*)base)[i];
    return ((const int*)base)[i];
}

// ---------------------------------------------------------------------------
// Zero a float buffer (float4 stores)
// ---------------------------------------------------------------------------
__global__ void zero_kernel(float4* __restrict__ p, int n4) {
    int i = blockIdx.x * blockDim.x + threadIdx.x;
    int stride = gridDim.x * blockDim.x;
    for (; i < n4; i += stride) p[i] = make_float4(0.f, 0.f, 0.f, 0.f);
}

// ---------------------------------------------------------------------------
// Edge scatter: one warp per edge. Gather x[src] (coalesced float4s),
// vector-reduce into sum[dst] with red.global.add.v4.f32.
// count_deg: lane 0 also bumps g_deg[dst] (layer 1 only).
// ---------------------------------------------------------------------------
template<int D, bool COUNT_DEG>
__global__ void scatter_kernel(const float* __restrict__ x,
                               const void* __restrict__ edge_base,
                               float* __restrict__ sum,
                               int n_edges) {
    int warp = (blockIdx.x * blockDim.x + threadIdx.x) >> 5;
    int lane = threadIdx.x & 31;
    if (warp >= n_edges) return;
    int s = load_idx(edge_base, warp);             // src row
    int d = load_idx(edge_base, N_EDGES + warp);   // dst row
    if (COUNT_DEG && lane == 0) atomicAdd(&g_deg[d], 1.0f);

    const float4* xs = (const float4*)(x + (size_t)s * D);
    float* db = sum + (size_t)d * D;
#pragma unroll
    for (int i = 0; i < D / 128; i++) {
        float4 v = xs[lane + i * 32];
        float* addr = db + (size_t)(lane + i * 32) * 4;
        asm volatile("red.global.add.v4.f32 [%0], {%1, %2, %3, %4};"
                     :: "l"(addr), "f"(v.x), "f"(v.y), "f"(v.z), "f"(v.w)
                     : "memory");
    }
}

// ---------------------------------------------------------------------------
// Scale rows by 1/max(deg, 1)  (mean aggregation)
// ---------------------------------------------------------------------------
template<int D>
__global__ void scale_kernel(float* __restrict__ agg) {
    int i = blockIdx.x * blockDim.x + threadIdx.x;   // over N*D/4
    const int n4 = N_NODES * (D / 4);
    if (i >= n4) return;
    int row = i / (D / 4);
    float inv = 1.0f / fmaxf(g_deg[row], 1.0f);
    float4 v = ((float4*)agg)[i];
    v.x *= inv; v.y *= inv; v.z *= inv; v.w *= inv;
    ((float4*)agg)[i] = v;
}

// ---------------------------------------------------------------------------
// Fused SGEMM:  C = relu(A1 @ B1^T + A2 @ B2^T + bias)
// A1, A2: [M, K] row-major.  B1, B2: [256, K] row-major.  C: [M, 256].
// Tile 128x128x8, 256 threads, 8x8 per thread.
// ---------------------------------------------------------------------------
template<int K>
__global__ __launch_bounds__(256, 2)
void sage_gemm_kernel(const float* __restrict__ A1, const float* __restrict__ A2,
                      const float* __restrict__ B1, const float* __restrict__ B2,
                      const float* __restrict__ bias, float* __restrict__ C,
                      int M) {
    constexpr int BM = 128, BN = 128, BK = 8, NN = 256;
    __shared__ float As[BK][BM];
    __shared__ float Bs[BK][BN];

    const int tid = threadIdx.x;
    const int bm = blockIdx.x * BM;
    const int bn = blockIdx.y * BN;
    const int a_row = tid >> 1;            // 0..127
    const int a_col = (tid & 1) * 4;       // 0 or 4
    const int tx = tid & 15, ty = tid >> 4;

    float acc[8][8];
#pragma unroll
    for (int i = 0; i < 8; i++)
#pragma unroll
        for (int j = 0; j < 8; j++) acc[i][j] = 0.f;

    const int gm = bm + a_row;
    const bool arow_ok = (gm < M);
    const int gn = bn + a_row;             // always < 256

    for (int k0 = 0; k0 < 2 * K; k0 += BK) {
        const float* A = (k0 < K) ? A1 : A2;
        const float* B = (k0 < K) ? B1 : B2;
        const int ks = (k0 < K) ? k0 : (k0 - K);

        float4 av = arow_ok
            ? *(const float4*)&A[(size_t)gm * K + ks + a_col]
            : make_float4(0.f, 0.f, 0.f, 0.f);
        float4 bv = *(const float4*)&B[(size_t)gn * K + ks + a_col];

        __syncthreads();
        As[a_col + 0][a_row] = av.x;
        As[a_col + 1][a_row] = av.y;
        As[a_col + 2][a_row] = av.z;
        As[a_col + 3][a_row] = av.w;
        Bs[a_col + 0][a_row] = bv.x;
        Bs[a_col + 1][a_row] = bv.y;
        Bs[a_col + 2][a_row] = bv.z;
        Bs[a_col + 3][a_row] = bv.w;
        __syncthreads();

#pragma unroll
        for (int k = 0; k < BK; k++) {
            float4 a0 = *(const float4*)&As[k][ty * 8];
            float4 a1 = *(const float4*)&As[k][ty * 8 + 4];
            float4 b0 = *(const float4*)&Bs[k][tx * 8];
            float4 b1 = *(const float4*)&Bs[k][tx * 8 + 4];
            float ar[8] = {a0.x, a0.y, a0.z, a0.w, a1.x, a1.y, a1.z, a1.w};
            float br[8] = {b0.x, b0.y, b0.z, b0.w, b1.x, b1.y, b1.z, b1.w};
#pragma unroll
            for (int i = 0; i < 8; i++)
#pragma unroll
                for (int j = 0; j < 8; j++)
                    acc[i][j] = fmaf(ar[i], br[j], acc[i][j]);
        }
    }

#pragma unroll
    for (int i = 0; i < 8; i++) {
        int r = bm + ty * 8 + i;
        if (r >= M) break;
#pragma unroll
        for (int j = 0; j < 8; j += 4) {
            int c = bn + tx * 8 + j;
            float4 v;
            v.x = fmaxf(acc[i][j + 0] + bias[c + 0], 0.f);
            v.y = fmaxf(acc[i][j + 1] + bias[c + 1], 0.f);
            v.z = fmaxf(acc[i][j + 2] + bias[c + 2], 0.f);
            v.w = fmaxf(acc[i][j + 3] + bias[c + 3], 0.f);
            *(float4*)&C[(size_t)r * NN + c] = v;
        }
    }
}

// ---------------------------------------------------------------------------
// Launch
// ---------------------------------------------------------------------------
extern "C" void kernel_launch(void* const* d_in, const int* in_sizes, int n_in,
                              void* d_out, int out_size) {
    const float* x    = (const float*)d_in[0];
    const void*  ei   = d_in[1];                 // int64 or int32, detected on-device
    const float* w_l1 = (const float*)d_in[2];
    const float* b_l1 = (const float*)d_in[3];
    const float* w_r1 = (const float*)d_in[4];
    const float* w_l2 = (const float*)d_in[5];
    const float* b_l2 = (const float*)d_in[6];
    const float* w_r2 = (const float*)d_in[7];
    float* out = (float*)d_out;

    float *agg1, *agg2, *h, *deg;
    cudaGetSymbolAddress((void**)&agg1, g_agg1);
    cudaGetSymbolAddress((void**)&agg2, g_agg2);
    cudaGetSymbolAddress((void**)&h,    g_h);
    cudaGetSymbolAddress((void**)&deg,  g_deg);

    // Detect edge index width
    detect_idx_kernel<<<1, 256>>>((const long long*)ei);

    // Zero scratch (agg1, agg2, deg)
    {
        int n4 = N_NODES * D_IN / 4;
        zero_kernel<<<(n4 + 255) / 256, 256>>>((float4*)agg1, n4);
        n4 = N_NODES * D_HID / 4;
        zero_kernel<<<(n4 + 255) / 256, 256>>>((float4*)agg2, n4);
        n4 = N_NODES / 4;
        zero_kernel<<<(n4 + 255) / 256, 256>>>((float4*)deg, n4);
    }

    const int scatter_blocks = (N_EDGES * 32) / 256;   // one warp per edge

    // Layer 1: aggregate x, then fused GEMM -> h
    scatter_kernel<D_IN, true><<<scatter_blocks, 256>>>(x, ei, agg1, N_EDGES);
    {
        int n = N_NODES * (D_IN / 4);
        scale_kernel<D_IN><<<(n + 255) / 256, 256>>>(agg1);
    }
    {
        dim3 grid((N_NODES + 127) / 128, D_HID / 128);
        sage_gemm_kernel<D_IN><<<grid, 256>>>(agg1, x, w_l1, w_r1, b_l1, h, N_NODES);
    }

    // Layer 2: aggregate h, then fused GEMM -> out
    scatter_kernel<D_HID, false><<<scatter_blocks, 256>>>(h, ei, agg2, N_EDGES);
    {
        int n = N_NODES * (D_HID / 4);
        scale_kernel<D_HID><<<(n + 255) / 256, 256>>>(agg2);
    }
    {
        dim3 grid((N_NODES + 127) / 128, D_OUT / 128);
        sage_gemm_kernel<D_HID><<<grid, 256>>>(agg2, h, w_l2, w_r2, b_l2, out, N_NODES);
    }
}

// round 4
// speedup vs baseline: 1.6197x; 1.6197x over previous
#include <cuda_runtime.h>
#include <cuda_bf16.h>
#include <cstdint>

// Problem constants
#define N_NODES 50000
#define N_EDGES 800000
#define D_IN    128
#define D_HID   256
#define D_OUT   256

// ---------------------------------------------------------------------------
// Scratch (__device__ globals; no allocation allowed)
// ---------------------------------------------------------------------------
__device__ float g_deg[N_NODES];
__device__ float g_agg1[(size_t)N_NODES * D_IN];
__device__ float g_h[(size_t)N_NODES * D_HID];
__device__ float g_agg2[(size_t)N_NODES * D_HID];
__device__ int   g_is64;

#define BF16ARR __device__ __align__(16) __nv_bfloat16
BF16ARR g_xh [(size_t)N_NODES * D_IN];
BF16ARR g_xl [(size_t)N_NODES * D_IN];
BF16ARR g_a1h[(size_t)N_NODES * D_IN];
BF16ARR g_a1l[(size_t)N_NODES * D_IN];
BF16ARR g_hh [(size_t)N_NODES * D_HID];
BF16ARR g_hl [(size_t)N_NODES * D_HID];
BF16ARR g_a2h[(size_t)N_NODES * D_HID];
BF16ARR g_a2l[(size_t)N_NODES * D_HID];
BF16ARR g_wl1h[D_HID * D_IN];
BF16ARR g_wl1l[D_HID * D_IN];
BF16ARR g_wr1h[D_HID * D_IN];
BF16ARR g_wr1l[D_HID * D_IN];
BF16ARR g_wl2h[D_OUT * D_HID];
BF16ARR g_wl2l[D_OUT * D_HID];
BF16ARR g_wr2h[D_OUT * D_HID];
BF16ARR g_wr2l[D_OUT * D_HID];

// ---------------------------------------------------------------------------
// Small PTX helpers (all baseline sm_80+ -- no 'a' features)
// ---------------------------------------------------------------------------
__device__ __forceinline__ uint32_t smem_to_u32(const void* p) {
    uint32_t a;
    asm("{ .reg .u64 t; cvta.to.shared.u64 t, %1; cvt.u32.u64 %0, t; }" : "=r"(a) : "l"(p));
    return a;
}
__device__ __forceinline__ void cp_async16(uint32_t dst, const void* src, bool valid) {
    int sz = valid ? 16 : 0;
    asm volatile("cp.async.cg.shared.global [%0], [%1], 16, %2;"
                 :: "r"(dst), "l"(src), "r"(sz) : "memory");
}
__device__ __forceinline__ void cp_commit() {
    asm volatile("cp.async.commit_group;" ::: "memory");
}
__device__ __forceinline__ void ldsm_x4(uint32_t* r, uint32_t addr) {
    asm volatile("ldmatrix.sync.aligned.m8n8.x4.shared.b16 {%0,%1,%2,%3}, [%4];"
                 : "=r"(r[0]), "=r"(r[1]), "=r"(r[2]), "=r"(r[3]) : "r"(addr));
}
__device__ __forceinline__ void mma16816(float* d, const uint32_t* a,
                                         uint32_t b0, uint32_t b1) {
    asm volatile("mma.sync.aligned.m16n8k16.row.col.f32.bf16.bf16.f32 "
                 "{%0,%1,%2,%3}, {%4,%5,%6,%7}, {%8,%9}, {%0,%1,%2,%3};"
                 : "+f"(d[0]), "+f"(d[1]), "+f"(d[2]), "+f"(d[3])
                 : "r"(a[0]), "r"(a[1]), "r"(a[2]), "r"(a[3]), "r"(b0), "r"(b1));
}

// ---------------------------------------------------------------------------
// Edge-index dtype detection (int64 vs int32)
// ---------------------------------------------------------------------------
__global__ void detect_idx_kernel(const long long* __restrict__ p) {
    __shared__ int bad;
    if (threadIdx.x == 0) bad = 0;
    __syncthreads();
    for (int i = threadIdx.x; i < 4096; i += blockDim.x) {
        long long v = p[i];
        if (v < 0 || v >= N_NODES) bad = 1;
    }
    __syncthreads();
    if (threadIdx.x == 0) g_is64 = bad ? 0 : 1;
}
__device__ __forceinline__ int load_idx(const void* base, int i) {
    if (g_is64) return (int)((const long long*)base)[i];
    return ((const int*)base)[i];
}

__global__ void zero_kernel(float4* __restrict__ p, int n4) {
    int i = blockIdx.x * blockDim.x + threadIdx.x;
    int stride = gridDim.x * blockDim.x;
    for (; i < n4; i += stride) p[i] = make_float4(0.f, 0.f, 0.f, 0.f);
}

// ---------------------------------------------------------------------------
// Edge scatter: one warp per edge, red.global.add.v4.f32
// ---------------------------------------------------------------------------
template<int D, bool COUNT_DEG>
__global__ void scatter_kernel(const float* __restrict__ x,
                               const void* __restrict__ edge_base,
                               float* __restrict__ sum, int n_edges) {
    int warp = (blockIdx.x * blockDim.x + threadIdx.x) >> 5;
    int lane = threadIdx.x & 31;
    if (warp >= n_edges) return;
    int s = load_idx(edge_base, warp);
    int d = load_idx(edge_base, N_EDGES + warp);
    if (COUNT_DEG && lane == 0) atomicAdd(&g_deg[d], 1.0f);
    const float4* xs = (const float4*)(x + (size_t)s * D);
    float* db = sum + (size_t)d * D;
#pragma unroll
    for (int i = 0; i < D / 128; i++) {
        float4 v = xs[lane + i * 32];
        float* addr = db + (size_t)(lane + i * 32) * 4;
        asm volatile("red.global.add.v4.f32 [%0], {%1, %2, %3, %4};"
                     :: "l"(addr), "f"(v.x), "f"(v.y), "f"(v.z), "f"(v.w) : "memory");
    }
}

// ---------------------------------------------------------------------------
// fp32 -> bf16 hi/lo split (optionally scale by 1/max(deg,1))
// ---------------------------------------------------------------------------
__device__ __forceinline__ uint32_t pack_bf(__nv_bfloat16 a, __nv_bfloat16 b) {
    __nv_bfloat162 t = __halves2bfloat162(a, b);
    return *(uint32_t*)&t;
}
template<bool USE_DEG>
__global__ void split_kernel(const float* __restrict__ src,
                             __nv_bfloat16* __restrict__ hi,
                             __nv_bfloat16* __restrict__ lo,
                             int n4, int dshift) {
    int i = blockIdx.x * blockDim.x + threadIdx.x;
    if (i >= n4) return;
    float inv = 1.0f;
    if (USE_DEG) inv = 1.0f / fmaxf(g_deg[i >> dshift], 1.0f);
    float4 v = ((const float4*)src)[i];
    v.x *= inv; v.y *= inv; v.z *= inv; v.w *= inv;
    __nv_bfloat16 h0 = __float2bfloat16(v.x), h1 = __float2bfloat16(v.y);
    __nv_bfloat16 h2 = __float2bfloat16(v.z), h3 = __float2bfloat16(v.w);
    __nv_bfloat16 l0 = __float2bfloat16(v.x - __bfloat162float(h0));
    __nv_bfloat16 l1 = __float2bfloat16(v.y - __bfloat162float(h1));
    __nv_bfloat16 l2 = __float2bfloat16(v.z - __bfloat162float(h2));
    __nv_bfloat16 l3 = __float2bfloat16(v.w - __bfloat162float(h3));
    ((uint2*)hi)[i] = make_uint2(pack_bf(h0, h1), pack_bf(h2, h3));
    ((uint2*)lo)[i] = make_uint2(pack_bf(l0, l1), pack_bf(l2, l3));
}

// ---------------------------------------------------------------------------
// Warp-MMA fused GEMM (mma.sync bf16, hi/lo split = 6 K-segments):
//   C[M,256] = relu( A1@B1^T + A2@B2^T + bias )
// CTA tile 128x128, 8 warps (4x2), warp tile 32x64, K chunk 64 (2-stage
// cp.async ring).  SMEM rows padded to 144B -> conflict-free ldmatrix.
// ---------------------------------------------------------------------------
#define PITCH 144
#define STAGE_A_BYTES (128 * PITCH)                 // 18432
#define STAGE_BYTES   (2 * 128 * PITCH)             // A + B = 36864
#define GEMM_SMEM     (2 * STAGE_BYTES)             // 73728

template<int K1, bool WRITE_H>
__global__ __launch_bounds__(256, 2)
void mma_gemm_kernel(const __nv_bfloat16* __restrict__ a1h, const __nv_bfloat16* __restrict__ a1l,
                     const __nv_bfloat16* __restrict__ a2h, const __nv_bfloat16* __restrict__ a2l,
                     const __nv_bfloat16* __restrict__ b1h, const __nv_bfloat16* __restrict__ b1l,
                     const __nv_bfloat16* __restrict__ b2h, const __nv_bfloat16* __restrict__ b2l,
                     const float* __restrict__ bias, float* __restrict__ C,
                     __nv_bfloat16* __restrict__ Hh, __nv_bfloat16* __restrict__ Hl, int M) {
    extern __shared__ char smem[];
    constexpr int NCH  = K1 / 64;       // chunks per segment
    constexpr int CTOT = 6 * NCH;       // total K chunks

    const uint32_t smem_base = smem_to_u32(smem);
    const int tid  = threadIdx.x;
    const int wid  = tid >> 5, lane = tid & 31;
    const int wm   = wid & 3, wn = wid >> 2;        // warp grid 4 x 2
    const int m0   = blockIdx.x * 128;
    const int bn0  = blockIdx.y * 128;

    const __nv_bfloat16* SA[6] = {a1h, a1h, a1l, a2h, a2h, a2l};
    const __nv_bfloat16* SB[6] = {b1h, b1l, b1h, b2h, b2l, b2h};

    float acc[2][8][4];
#pragma unroll
    for (int i = 0; i < 2; i++)
#pragma unroll
        for (int j = 0; j < 8; j++)
#pragma unroll
            for (int r = 0; r < 4; r++) acc[i][j][r] = 0.f;

    // ---- chunk issue via cp.async ----
    auto issue = [&](int c, int stg) {
        const __nv_bfloat16* Ap = SA[c / NCH];
        const __nv_bfloat16* Bp = SB[c / NCH];
        const int k0 = (c % NCH) * 64;
        const uint32_t sa = smem_base + stg * STAGE_BYTES;
        const uint32_t sb = sa + STAGE_A_BYTES;
#pragma unroll
        for (int it = 0; it < 4; it++) {
            int idx = tid + it * 256;
            int row = idx >> 3, ch = idx & 7;
            int gm = m0 + row;
            cp_async16(sa + row * PITCH + ch * 16,
                       Ap + (size_t)gm * K1 + k0 + ch * 8, gm < M);
            cp_async16(sb + row * PITCH + ch * 16,
                       Bp + (size_t)(bn0 + row) * K1 + k0 + ch * 8, true);
        }
        cp_commit();
    };

    issue(0, 0);

    const int arow = wm * 32 + (lane & 15);
    const int brow = wn * 64 + (lane & 15);
    const int chi  = lane >> 4;

    for (int c = 0; c < CTOT; c++) {
        const int s = c & 1;
        if (c + 1 < CTOT) issue(c + 1, s ^ 1);

        if (c + 1 < CTOT) asm volatile("cp.async.wait_group 1;" ::: "memory");
        else              asm volatile("cp.async.wait_group 0;" ::: "memory");
        __syncthreads();

        const uint32_t sa = smem_base + s * STAGE_BYTES;
        const uint32_t sb = sa + STAGE_A_BYTES;
#pragma unroll
        for (int kk = 0; kk < 4; kk++) {
            uint32_t a[2][4], b[4][4];
#pragma unroll
            for (int am = 0; am < 2; am++)
                ldsm_x4(a[am], sa + (uint32_t)(arow + am * 16) * PITCH
                                  + (uint32_t)(kk * 2 + chi) * 16);
#pragma unroll
            for (int bi = 0; bi < 4; bi++)
                ldsm_x4(b[bi], sb + (uint32_t)(brow + bi * 16) * PITCH
                                  + (uint32_t)(kk * 2 + chi) * 16);
#pragma unroll
            for (int am = 0; am < 2; am++)
#pragma unroll
                for (int bi = 0; bi < 4; bi++) {
                    mma16816(acc[am][2 * bi + 0], a[am], b[bi][0], b[bi][2]);
                    mma16816(acc[am][2 * bi + 1], a[am], b[bi][1], b[bi][3]);
                }
        }
        __syncthreads();
    }

    // ---- epilogue: bias + relu (+ optional bf16 hi/lo emission of H) ----
#pragma unroll
    for (int am = 0; am < 2; am++) {
        int gm = m0 + wm * 32 + am * 16 + (lane >> 2);
#pragma unroll
        for (int bi = 0; bi < 8; bi++) {
            int gn = bn0 + wn * 64 + bi * 8 + (lane & 3) * 2;
            float bz0 = bias[gn], bz1 = bias[gn + 1];
#pragma unroll
            for (int half = 0; half < 2; half++) {
                int r = gm + half * 8;
                if (r >= M) continue;
                float v0 = fmaxf(acc[am][bi][2 * half + 0] + bz0, 0.f);
                float v1 = fmaxf(acc[am][bi][2 * half + 1] + bz1, 0.f);
                *(float2*)(C + (size_t)r * 256 + gn) = make_float2(v0, v1);
                if (WRITE_H) {
                    __nv_bfloat16 h0 = __float2bfloat16(v0);
                    __nv_bfloat16 h1 = __float2bfloat16(v1);
                    __nv_bfloat16 l0 = __float2bfloat16(v0 - __bfloat162float(h0));
                    __nv_bfloat16 l1 = __float2bfloat16(v1 - __bfloat162float(h1));
                    *(uint32_t*)(Hh + (size_t)r * 256 + gn) = pack_bf(h0, h1);
                    *(uint32_t*)(Hl + (size_t)r * 256 + gn) = pack_bf(l0, l1);
                }
            }
        }
    }
}

// ---------------------------------------------------------------------------
// Launch
// ---------------------------------------------------------------------------
extern "C" void kernel_launch(void* const* d_in, const int* in_sizes, int n_in,
                              void* d_out, int out_size) {
    const float* x    = (const float*)d_in[0];
    const void*  ei   = d_in[1];
    const float* w_l1 = (const float*)d_in[2];
    const float* b_l1 = (const float*)d_in[3];
    const float* w_r1 = (const float*)d_in[4];
    const float* w_l2 = (const float*)d_in[5];
    const float* b_l2 = (const float*)d_in[6];
    const float* w_r2 = (const float*)d_in[7];
    float* out = (float*)d_out;

    float *agg1, *agg2, *h, *deg;
    cudaGetSymbolAddress((void**)&agg1, g_agg1);
    cudaGetSymbolAddress((void**)&agg2, g_agg2);
    cudaGetSymbolAddress((void**)&h,    g_h);
    cudaGetSymbolAddress((void**)&deg,  g_deg);
    __nv_bfloat16 *xh, *xl, *a1h, *a1l, *hh, *hl, *a2h, *a2l;
    __nv_bfloat16 *wl1h, *wl1l, *wr1h, *wr1l, *wl2h, *wl2l, *wr2h, *wr2l;
    cudaGetSymbolAddress((void**)&xh,  g_xh);   cudaGetSymbolAddress((void**)&xl,  g_xl);
    cudaGetSymbolAddress((void**)&a1h, g_a1h);  cudaGetSymbolAddress((void**)&a1l, g_a1l);
    cudaGetSymbolAddress((void**)&hh,  g_hh);   cudaGetSymbolAddress((void**)&hl,  g_hl);
    cudaGetSymbolAddress((void**)&a2h, g_a2h);  cudaGetSymbolAddress((void**)&a2l, g_a2l);
    cudaGetSymbolAddress((void**)&wl1h, g_wl1h); cudaGetSymbolAddress((void**)&wl1l, g_wl1l);
    cudaGetSymbolAddress((void**)&wr1h, g_wr1h); cudaGetSymbolAddress((void**)&wr1l, g_wr1l);
    cudaGetSymbolAddress((void**)&wl2h, g_wl2h); cudaGetSymbolAddress((void**)&wl2l, g_wl2l);
    cudaGetSymbolAddress((void**)&wr2h, g_wr2h); cudaGetSymbolAddress((void**)&wr2l, g_wr2l);

    cudaFuncSetAttribute(mma_gemm_kernel<D_IN,  true >,
                         cudaFuncAttributeMaxDynamicSharedMemorySize, GEMM_SMEM);
    cudaFuncSetAttribute(mma_gemm_kernel<D_HID, false>,
                         cudaFuncAttributeMaxDynamicSharedMemorySize, GEMM_SMEM);

    detect_idx_kernel<<<1, 256>>>((const long long*)ei);

    // zero accumulators + degree
    {
        int n4 = N_NODES * D_IN / 4;
        zero_kernel<<<(n4 + 255) / 256, 256>>>((float4*)agg1, n4);
        n4 = N_NODES * D_HID / 4;
        zero_kernel<<<(n4 + 255) / 256, 256>>>((float4*)agg2, n4);
        n4 = N_NODES / 4;
        zero_kernel<<<(n4 + 255) / 256, 256>>>((float4*)deg, n4);
    }

    // split x and weights to bf16 hi/lo
    {
        int n4 = N_NODES * D_IN / 4;
        split_kernel<false><<<(n4 + 255) / 256, 256>>>(x, xh, xl, n4, 0);
        n4 = D_HID * D_IN / 4;
        split_kernel<false><<<(n4 + 255) / 256, 256>>>(w_l1, wl1h, wl1l, n4, 0);
        split_kernel<false><<<(n4 + 255) / 256, 256>>>(w_r1, wr1h, wr1l, n4, 0);
        n4 = D_OUT * D_HID / 4;
        split_kernel<false><<<(n4 + 255) / 256, 256>>>(w_l2, wl2h, wl2l, n4, 0);
        split_kernel<false><<<(n4 + 255) / 256, 256>>>(w_r2, wr2h, wr2l, n4, 0);
    }

    const int scatter_blocks = (N_EDGES * 32) / 256;
    const dim3 gemm_grid((N_NODES + 127) / 128, 2);

    // Layer 1
    scatter_kernel<D_IN, true><<<scatter_blocks, 256>>>(x, ei, agg1, N_EDGES);
    {
        int n4 = N_NODES * D_IN / 4;   // dshift = log2(D_IN/4) = 5
        split_kernel<true><<<(n4 + 255) / 256, 256>>>(agg1, a1h, a1l, n4, 5);
    }
    mma_gemm_kernel<D_IN, true><<<gemm_grid, 256, GEMM_SMEM>>>(
        a1h, a1l, xh, xl, wl1h, wl1l, wr1h, wr1l, b_l1, h, hh, hl, N_NODES);

    // Layer 2
    scatter_kernel<D_HID, false><<<scatter_blocks, 256>>>(h, ei, agg2, N_EDGES);
    {
        int n4 = N_NODES * D_HID / 4;  // dshift = log2(D_HID/4) = 6
        split_kernel<true><<<(n4 + 255) / 256, 256>>>(agg2, a2h, a2l, n4, 6);
    }
    mma_gemm_kernel<D_HID, false><<<gemm_grid, 256, GEMM_SMEM>>>(
        a2h, a2l, hh, hl, wl2h, wl2l, wr2h, wr2l, b_l2, out, nullptr, nullptr, N_NODES);
}

// round 6
// speedup vs baseline: 1.7159x; 1.0594x over previous
#include <cuda_runtime.h>
#include <cuda_fp16.h>
#include <cstdint>

// Problem constants
#define N_NODES 50000
#define N_EDGES 800000
#define D_IN    128
#define D_HID   256
#define D_OUT   256

// ---------------------------------------------------------------------------
// Scratch (__device__ globals; no allocation allowed)
// ---------------------------------------------------------------------------
__device__ float g_deg[N_NODES];
__device__ float g_agg1[(size_t)N_NODES * D_IN];     // fp32 sums (layer 1)
__device__ float g_agg2[(size_t)N_NODES * D_HID];    // fp32 sums (layer 2)
__device__ int   g_is64;

#define F16ARR __device__ __align__(16) __half
F16ARR g_x16 [(size_t)N_NODES * D_IN];    // x in fp16
F16ARR g_a116[(size_t)N_NODES * D_IN];    // agg1 (mean) in fp16
F16ARR g_h16 [(size_t)N_NODES * D_HID];   // h = relu(layer1) in fp16
F16ARR g_a216[(size_t)N_NODES * D_HID];   // agg2 (mean) in fp16
F16ARR g_wl1h[D_HID * D_IN];
F16ARR g_wl1l[D_HID * D_IN];
F16ARR g_wr1h[D_HID * D_IN];
F16ARR g_wr1l[D_HID * D_IN];
F16ARR g_wl2h[D_OUT * D_HID];
F16ARR g_wl2l[D_OUT * D_HID];
F16ARR g_wr2h[D_OUT * D_HID];
F16ARR g_wr2l[D_OUT * D_HID];

// ---------------------------------------------------------------------------
// PTX helpers (baseline sm_80+; no sm_103a-gated features)
// ---------------------------------------------------------------------------
__device__ __forceinline__ uint32_t smem_to_u32(const void* p) {
    uint32_t a;
    asm("{ .reg .u64 t; cvta.to.shared.u64 t, %1; cvt.u32.u64 %0, t; }" : "=r"(a) : "l"(p));
    return a;
}
__device__ __forceinline__ void cp_async16(uint32_t dst, const void* src, bool valid) {
    int sz = valid ? 16 : 0;
    asm volatile("cp.async.cg.shared.global [%0], [%1], 16, %2;"
                 :: "r"(dst), "l"(src), "r"(sz) : "memory");
}
__device__ __forceinline__ void cp_commit() {
    asm volatile("cp.async.commit_group;" ::: "memory");
}
__device__ __forceinline__ void ldsm_x4(uint32_t* r, uint32_t addr) {
    asm volatile("ldmatrix.sync.aligned.m8n8.x4.shared.b16 {%0,%1,%2,%3}, [%4];"
                 : "=r"(r[0]), "=r"(r[1]), "=r"(r[2]), "=r"(r[3]) : "r"(addr));
}
__device__ __forceinline__ void mma16816(float* d, const uint32_t* a,
                                         uint32_t b0, uint32_t b1) {
    asm volatile("mma.sync.aligned.m16n8k16.row.col.f32.f16.f16.f32 "
                 "{%0,%1,%2,%3}, {%4,%5,%6,%7}, {%8,%9}, {%0,%1,%2,%3};"
                 : "+f"(d[0]), "+f"(d[1]), "+f"(d[2]), "+f"(d[3])
                 : "r"(a[0]), "r"(a[1]), "r"(a[2]), "r"(a[3]), "r"(b0), "r"(b1));
}
__device__ __forceinline__ void red_v4(float* addr, float a, float b, float c, float d) {
    asm volatile("red.global.add.v4.f32 [%0], {%1, %2, %3, %4};"
                 :: "l"(addr), "f"(a), "f"(b), "f"(c), "f"(d) : "memory");
}

// ---------------------------------------------------------------------------
// Edge-index dtype detection (int64 vs int32)
// ---------------------------------------------------------------------------
__global__ void detect_idx_kernel(const long long* __restrict__ p) {
    __shared__ int bad;
    if (threadIdx.x == 0) bad = 0;
    __syncthreads();
    for (int i = threadIdx.x; i < 4096; i += blockDim.x) {
        long long v = p[i];
        if (v < 0 || v >= N_NODES) bad = 1;
    }
    __syncthreads();
    if (threadIdx.x == 0) g_is64 = bad ? 0 : 1;
}
__device__ __forceinline__ int load_idx(const void* base, int i) {
    if (g_is64) return (int)((const long long*)base)[i];
    return ((const int*)base)[i];
}

// ---------------------------------------------------------------------------
// Zero agg1, agg2, deg in one kernel (grid-stride over combined float4 range)
// ---------------------------------------------------------------------------
#define N4_A1  (N_NODES * D_IN / 4)        // 1,600,000
#define N4_A2  (N_NODES * D_HID / 4)       // 3,200,000
#define N4_DEG (N_NODES / 4)               // 12,500
__global__ void zeros_kernel(float4* a1, float4* a2, float4* dg) {
    const float4 z = make_float4(0.f, 0.f, 0.f, 0.f);
    int stride = gridDim.x * blockDim.x;
    for (int i = blockIdx.x * blockDim.x + threadIdx.x;
         i < N4_A1 + N4_A2 + N4_DEG; i += stride) {
        if (i < N4_A1) a1[i] = z;
        else if (i < N4_A1 + N4_A2) a2[i - N4_A1] = z;
        else dg[i - N4_A1 - N4_A2] = z;
    }
}

// ---------------------------------------------------------------------------
// Prep: x -> fp16, weights -> fp16 hi/lo (one kernel, index ranges)
// ---------------------------------------------------------------------------
#define N4_X   (N_NODES * D_IN / 4)
#define N4_W1  (D_HID * D_IN / 4)     // 8192
#define N4_W2  (D_OUT * D_HID / 4)    // 16384
__device__ __forceinline__ uint2 to_h4(float4 v) {
    __half2 p0 = __floats2half2_rn(v.x, v.y);
    __half2 p1 = __floats2half2_rn(v.z, v.w);
    return make_uint2(*(uint32_t*)&p0, *(uint32_t*)&p1);
}
__device__ __forceinline__ void split_h4(float4 v, uint2& hi, uint2& lo) {
    __half h0 = __float2half_rn(v.x), h1 = __float2half_rn(v.y);
    __half h2 = __float2half_rn(v.z), h3 = __float2half_rn(v.w);
    __half l0 = __float2half_rn(v.x - __half2float(h0));
    __half l1 = __float2half_rn(v.y - __half2float(h1));
    __half l2 = __float2half_rn(v.z - __half2float(h2));
    __half l3 = __float2half_rn(v.w - __half2float(h3));
    __half2 ph0 = __halves2half2(h0, h1), ph1 = __halves2half2(h2, h3);
    __half2 pl0 = __halves2half2(l0, l1), pl1 = __halves2half2(l2, l3);
    hi = make_uint2(*(uint32_t*)&ph0, *(uint32_t*)&ph1);
    lo = make_uint2(*(uint32_t*)&pl0, *(uint32_t*)&pl1);
}
__global__ void prep_kernel(const float* x,
                            const float* wl1, const float* wr1,
                            const float* wl2, const float* wr2,
                            __half* x16,
                            __half* wl1h, __half* wl1l, __half* wr1h, __half* wr1l,
                            __half* wl2h, __half* wl2l, __half* wr2h, __half* wr2l) {
    int i = blockIdx.x * blockDim.x + threadIdx.x;
    if (i < N4_X) {
        ((uint2*)x16)[i] = to_h4(((const float4*)x)[i]);
        return;
    }
    int j = i - N4_X;
    const float* src; __half *ph, *pl;
    if (j < N4_W1)                { src = wl1; ph = wl1h; pl = wl1l; }
    else if (j < 2 * N4_W1)       { j -= N4_W1;   src = wr1; ph = wr1h; pl = wr1l; }
    else if (j < 2*N4_W1 + N4_W2) { j -= 2*N4_W1; src = wl2; ph = wl2h; pl = wl2l; }
    else if (j < 2*N4_W1 + 2*N4_W2){ j -= 2*N4_W1 + N4_W2; src = wr2; ph = wr2h; pl = wr2l; }
    else return;
    uint2 hi, lo;
    split_h4(((const float4*)src)[j], hi, lo);
    ((uint2*)ph)[j] = hi;
    ((uint2*)pl)[j] = lo;
}
#define PREP_TOTAL (N4_X + 2 * N4_W1 + 2 * N4_W2)

// ---------------------------------------------------------------------------
// Scatter layer 1: D=128, fp16 gather, fp32 red. 2 edges per warp (16 lanes
// each: 1 uint4 load = 8 halves -> 2 red.v4).  Also counts degree.
// ---------------------------------------------------------------------------
__global__ void scatter1_kernel(const __half* __restrict__ x16,
                                const void* __restrict__ ei,
                                float* __restrict__ sum) {
    int gwarp = (blockIdx.x * blockDim.x + threadIdx.x) >> 5;
    int lane = threadIdx.x & 31;
    int sub = lane >> 4, l16 = lane & 15;
    int e = gwarp * 2 + sub;
    if (e >= N_EDGES) return;
    int s = load_idx(ei, e);
    int d = load_idx(ei, N_EDGES + e);
    if (l16 == 0) atomicAdd(&g_deg[d], 1.0f);
    uint4 v = *(const uint4*)(x16 + (size_t)s * D_IN + l16 * 8);
    const __half2* hp = (const __half2*)&v;
    float2 f0 = __half22float2(hp[0]);
    float2 f1 = __half22float2(hp[1]);
    float2 f2 = __half22float2(hp[2]);
    float2 f3 = __half22float2(hp[3]);
    float* db = sum + (size_t)d * D_IN + l16 * 8;
    red_v4(db,     f0.x, f0.y, f1.x, f1.y);
    red_v4(db + 4, f2.x, f2.y, f3.x, f3.y);
}

// ---------------------------------------------------------------------------
// Scatter layer 2: D=256, fp16 gather of h, fp32 red. 1 edge per warp
// (32 lanes x 8 halves = 256).
// ---------------------------------------------------------------------------
__global__ void scatter2_kernel(const __half* __restrict__ h16,
                                const void* __restrict__ ei,
                                float* __restrict__ sum) {
    int warp = (blockIdx.x * blockDim.x + threadIdx.x) >> 5;
    int lane = threadIdx.x & 31;
    if (warp >= N_EDGES) return;
    int s = load_idx(ei, warp);
    int d = load_idx(ei, N_EDGES + warp);
    uint4 v = *(const uint4*)(h16 + (size_t)s * D_HID + lane * 8);
    const __half2* hp = (const __half2*)&v;
    float2 f0 = __half22float2(hp[0]);
    float2 f1 = __half22float2(hp[1]);
    float2 f2 = __half22float2(hp[2]);
    float2 f3 = __half22float2(hp[3]);
    float* db = sum + (size_t)d * D_HID + lane * 8;
    red_v4(db,     f0.x, f0.y, f1.x, f1.y);
    red_v4(db + 4, f2.x, f2.y, f3.x, f3.y);
}

// ---------------------------------------------------------------------------
// fp32 agg -> fp16 mean (scale by 1/max(deg,1))
// ---------------------------------------------------------------------------
__global__ void cvt_kernel(const float* __restrict__ src,
                           __half* __restrict__ dst, int n4, int dshift) {
    int i = blockIdx.x * blockDim.x + threadIdx.x;
    if (i >= n4) return;
    float inv = 1.0f / fmaxf(g_deg[i >> dshift], 1.0f);
    float4 v = ((const float4*)src)[i];
    v.x *= inv; v.y *= inv; v.z *= inv; v.w *= inv;
    ((uint2*)dst)[i] = to_h4(v);
}

// ---------------------------------------------------------------------------
// fp16 2-pass fused GEMM:
//   C[M,256] = relu( A1@(B1h+B1l)^T + A2@(B2h+B2l)^T + bias )
// A1, A2 fp16 [M,K1]; B* fp16 [256,K1].  CTA tile 128x128, 8 warps (4x2),
// warp tile 32x64, K chunk 64, 2-stage cp.async ring, pitch 144 (no conflicts).
// Per chunk: A loaded once, MMA'd against Bh then Bl (same accumulators).
// F16OUT: write fp16 H (layer 1); else write fp32 C (layer 2).
// ---------------------------------------------------------------------------
#define PITCH 144
#define TILE_BYTES (128 * PITCH)                  // 18432
#define STAGE_BYTES (3 * TILE_BYTES)              // A + Bh + Bl = 55296
#define GEMM_SMEM (2 * STAGE_BYTES)               // 110592

template<int K1, bool F16OUT>
__global__ __launch_bounds__(256, 2)
void gemm2p_kernel(const __half* __restrict__ A1, const __half* __restrict__ A2,
                   const __half* __restrict__ B1h, const __half* __restrict__ B1l,
                   const __half* __restrict__ B2h, const __half* __restrict__ B2l,
                   const float* __restrict__ bias, float* __restrict__ C,
                   __half* __restrict__ H, int M) {
    extern __shared__ char smem[];
    constexpr int NCH = K1 / 64;        // chunks per matrix
    constexpr int CT  = 2 * NCH;        // total chunks

    const uint32_t smem_base = smem_to_u32(smem);
    const int tid = threadIdx.x;
    const int wid = tid >> 5, lane = tid & 31;
    const int wm = wid & 3, wn = wid >> 2;
    const int m0  = blockIdx.x * 128;
    const int bn0 = blockIdx.y * 128;

    float acc[2][8][4];
#pragma unroll
    for (int i = 0; i < 2; i++)
#pragma unroll
        for (int j = 0; j < 8; j++)
#pragma unroll
            for (int r = 0; r < 4; r++) acc[i][j][r] = 0.f;

    auto issue = [&](int c, int stg) {
        const int mtx = c / NCH;
        const int k0 = (c % NCH) * 64;
        const __half* Ap = mtx ? A2 : A1;
        const __half* Bh = mtx ? B2h : B1h;
        const __half* Bl = mtx ? B2l : B1l;
        const uint32_t s0 = smem_base + stg * STAGE_BYTES;
#pragma unroll
        for (int it = 0; it < 4; it++) {
            int idx = tid + it * 256;
            int row = idx >> 3, ch = idx & 7;
            int gm = m0 + row;
            cp_async16(s0 + row * PITCH + ch * 16,
                       Ap + (size_t)gm * K1 + k0 + ch * 8, gm < M);
            cp_async16(s0 + TILE_BYTES + row * PITCH + ch * 16,
                       Bh + (size_t)(bn0 + row) * K1 + k0 + ch * 8, true);
            cp_async16(s0 + 2 * TILE_BYTES + row * PITCH + ch * 16,
                       Bl + (size_t)(bn0 + row) * K1 + k0 + ch * 8, true);
        }
        cp_commit();
    };

    issue(0, 0);

    const int arow = wm * 32 + (lane & 15);
    const int brow = wn * 64 + (lane & 15);
    const int chi  = lane >> 4;

    for (int c = 0; c < CT; c++) {
        const int s = c & 1;
        if (c + 1 < CT) issue(c + 1, s ^ 1);

        if (c + 1 < CT) asm volatile("cp.async.wait_group 1;" ::: "memory");
        else            asm volatile("cp.async.wait_group 0;" ::: "memory");
        __syncthreads();

        const uint32_t sa = smem_base + s * STAGE_BYTES;
#pragma unroll
        for (int kk = 0; kk < 4; kk++) {
            uint32_t a[2][4];
#pragma unroll
            for (int am = 0; am < 2; am++)
                ldsm_x4(a[am], sa + (uint32_t)(arow + am * 16) * PITCH
                                  + (uint32_t)(kk * 2 + chi) * 16);
#pragma unroll
            for (int p = 0; p < 2; p++) {
                const uint32_t sb = sa + (1 + p) * TILE_BYTES;
                uint32_t b[4][4];
#pragma unroll
                for (int bi = 0; bi < 4; bi++)
                    ldsm_x4(b[bi], sb + (uint32_t)(brow + bi * 16) * PITCH
                                      + (uint32_t)(kk * 2 + chi) * 16);
#pragma unroll
                for (int am = 0; am < 2; am++)
#pragma unroll
                    for (int bi = 0; bi < 4; bi++) {
                        mma16816(acc[am][2 * bi + 0], a[am], b[bi][0], b[bi][2]);
                        mma16816(acc[am][2 * bi + 1], a[am], b[bi][1], b[bi][3]);
                    }
            }
        }
        __syncthreads();
    }

    // ---- epilogue: bias + relu; fp16 H or fp32 C ----
#pragma unroll
    for (int am = 0; am < 2; am++) {
        int gm = m0 + wm * 32 + am * 16 + (lane >> 2);
#pragma unroll
        for (int bi = 0; bi < 8; bi++) {
            int gn = bn0 + wn * 64 + bi * 8 + (lane & 3) * 2;
            float bz0 = bias[gn], bz1 = bias[gn + 1];
#pragma unroll
            for (int half = 0; half < 2; half++) {
                int r = gm + half * 8;
                if (r >= M) continue;
                float v0 = fmaxf(acc[am][bi][2 * half + 0] + bz0, 0.f);
                float v1 = fmaxf(acc[am][bi][2 * half + 1] + bz1, 0.f);
                if (F16OUT) {
                    __half2 p = __floats2half2_rn(v0, v1);
                    *(uint32_t*)(H + (size_t)r * 256 + gn) = *(uint32_t*)&p;
                } else {
                    *(float2*)(C + (size_t)r * 256 + gn) = make_float2(v0, v1);
                }
            }
        }
    }
}

// ---------------------------------------------------------------------------
// Launch
// ---------------------------------------------------------------------------
extern "C" void kernel_launch(void* const* d_in, const int* in_sizes, int n_in,
                              void* d_out, int out_size) {
    const float* x    = (const float*)d_in[0];
    const void*  ei   = d_in[1];
    const float* w_l1 = (const float*)d_in[2];
    const float* b_l1 = (const float*)d_in[3];
    const float* w_r1 = (const float*)d_in[4];
    const float* w_l2 = (const float*)d_in[5];
    const float* b_l2 = (const float*)d_in[6];
    const float* w_r2 = (const float*)d_in[7];
    float* out = (float*)d_out;

    float *agg1, *agg2, *deg;
    cudaGetSymbolAddress((void**)&agg1, g_agg1);
    cudaGetSymbolAddress((void**)&agg2, g_agg2);
    cudaGetSymbolAddress((void**)&deg,  g_deg);
    __half *x16, *a116, *h16, *a216;
    __half *wl1h, *wl1l, *wr1h, *wr1l, *wl2h, *wl2l, *wr2h, *wr2l;
    cudaGetSymbolAddress((void**)&x16,  g_x16);
    cudaGetSymbolAddress((void**)&a116, g_a116);
    cudaGetSymbolAddress((void**)&h16,  g_h16);
    cudaGetSymbolAddress((void**)&a216, g_a216);
    cudaGetSymbolAddress((void**)&wl1h, g_wl1h); cudaGetSymbolAddress((void**)&wl1l, g_wl1l);
    cudaGetSymbolAddress((void**)&wr1h, g_wr1h); cudaGetSymbolAddress((void**)&wr1l, g_wr1l);
    cudaGetSymbolAddress((void**)&wl2h, g_wl2h); cudaGetSymbolAddress((void**)&wl2l, g_wl2l);
    cudaGetSymbolAddress((void**)&wr2h, g_wr2h); cudaGetSymbolAddress((void**)&wr2l, g_wr2l);

    cudaFuncSetAttribute(gemm2p_kernel<D_IN,  true >,
                         cudaFuncAttributeMaxDynamicSharedMemorySize, GEMM_SMEM);
    cudaFuncSetAttribute(gemm2p_kernel<D_HID, false>,
                         cudaFuncAttributeMaxDynamicSharedMemorySize, GEMM_SMEM);

    detect_idx_kernel<<<1, 256>>>((const long long*)ei);
    zeros_kernel<<<1024, 256>>>((float4*)agg1, (float4*)agg2, (float4*)deg);
    prep_kernel<<<(PREP_TOTAL + 255) / 256, 256>>>(
        x, w_l1, w_r1, w_l2, w_r2, x16,
        wl1h, wl1l, wr1h, wr1l, wl2h, wl2l, wr2h, wr2l);

    const dim3 gemm_grid((N_NODES + 127) / 128, 2);

    // Layer 1
    scatter1_kernel<<<(N_EDGES / 2 * 32) / 256, 256>>>(x16, ei, agg1);
    cvt_kernel<<<(N4_A1 + 255) / 256, 256>>>(agg1, a116, N4_A1, 5);
    gemm2p_kernel<D_IN, true><<<gemm_grid, 256, GEMM_SMEM>>>(
        a116, x16, wl1h, wl1l, wr1h, wr1l, b_l1, nullptr, h16, N_NODES);

    // Layer 2
    scatter2_kernel<<<(N_EDGES * 32) / 256, 256>>>(h16, ei, agg2);
    cvt_kernel<<<(N4_A2 + 255) / 256, 256>>>(agg2, a216, N4_A2, 6);
    gemm2p_kernel<D_HID, false><<<gemm_grid, 256, GEMM_SMEM>>>(
        a216, h16, wl2h, wl2l, wr2h, wr2l, b_l2, out, nullptr, N_NODES);
}

// round 7
// speedup vs baseline: 3.7783x; 2.2019x over previous
#include <cuda_runtime.h>
#include <cuda_fp16.h>
#include <cstdint>

#define N_NODES 50000
#define N_EDGES 800000
#define D_IN    128
#define D_HID   256
#define D_OUT   256

__device__ int g_is64;
__device__ int g_hist[N_NODES];
__device__ int g_off[N_NODES + 1];
__device__ int g_cursor[N_NODES];
__device__ int g_bsum[64];
__device__ int g_csr[N_EDGES];

#define F16ARR __device__ __align__(16) __half
F16ARR g_x16 [(size_t)N_NODES * D_IN];
F16ARR g_a116[(size_t)N_NODES * D_IN];
F16ARR g_h16 [(size_t)N_NODES * D_HID];
F16ARR g_a216[(size_t)N_NODES * D_HID];
F16ARR g_wl1h[D_HID * D_IN];
F16ARR g_wl1l[D_HID * D_IN];
F16ARR g_wr1h[D_HID * D_IN];
F16ARR g_wr1l[D_HID * D_IN];
F16ARR g_wl2h[D_OUT * D_HID];
F16ARR g_wl2l[D_OUT * D_HID];
F16ARR g_wr2h[D_OUT * D_HID];
F16ARR g_wr2l[D_OUT * D_HID];

__device__ __forceinline__ uint32_t smem_to_u32(const void* p) {
    uint32_t a;
    asm("{ .reg .u64 t; cvta.to.shared.u64 t, %1; cvt.u32.u64 %0, t; }" : "=r"(a) : "l"(p));
    return a;
}
__device__ __forceinline__ void cp_async16(uint32_t dst, const void* src, bool valid) {
    int sz = valid ? 16 : 0;
    asm volatile("cp.async.cg.shared.global [%0], [%1], 16, %2;"
                 :: "r"(dst), "l"(src), "r"(sz) : "memory");
}
__device__ __forceinline__ void cp_commit() {
    asm volatile("cp.async.commit_group;" ::: "memory");
}
__device__ __forceinline__ void ldsm_x4(uint32_t* r, uint32_t addr) {
    asm volatile("ldmatrix.sync.aligned.m8n8.x4.shared.b16 {%0,%1,%2,%3}, [%4];"
                 : "=r"(r[0]), "=r"(r[1]), "=r"(r[2]), "=r"(r[3]) : "r"(addr));
}
__device__ __forceinline__ void mma16816(float* d, const uint32_t* a,
                                         uint32_t b0, uint32_t b1) {
    asm volatile("mma.sync.aligned.m16n8k16.row.col.f32.f16.f16.f32 "
                 "{%0,%1,%2,%3}, {%4,%5,%6,%7}, {%8,%9}, {%0,%1,%2,%3};"
                 : "+f"(d[0]), "+f"(d[1]), "+f"(d[2]), "+f"(d[3])
                 : "r"(a[0]), "r"(a[1]), "r"(a[2]), "r"(a[3]), "r"(b0), "r"(b1));
}

__global__ void detect_idx_kernel(const long long* __restrict__ p) {
    __shared__ int bad;
    if (threadIdx.x == 0) bad = 0;
    __syncthreads();
    for (int i = threadIdx.x; i < 4096; i += blockDim.x) {
        long long v = p[i];
        if (v < 0 || v >= N_NODES) bad = 1;
    }
    __syncthreads();
    if (threadIdx.x == 0) g_is64 = bad ? 0 : 1;
}
__device__ __forceinline__ int load_idx(const void* base, int i) {
    if (g_is64) return (int)((const long long*)base)[i];
    return ((const int*)base)[i];
}

// ---- CSR build ----
__global__ void zero_hist_kernel(int* hist) {
    int i = blockIdx.x * blockDim.x + threadIdx.x;
    if (i < N_NODES) hist[i] = 0;
}
__global__ void hist_kernel(const void* __restrict__ ei, int* __restrict__ hist) {
    int e = blockIdx.x * blockDim.x + threadIdx.x;
    if (e >= N_EDGES) return;
    atomicAdd(&hist[load_idx(ei, N_EDGES + e)], 1);
}
#define SCAN_NB ((N_NODES + 1023) / 1024)   // 49
__global__ void scan1_kernel(const int* __restrict__ hist,
                             int* __restrict__ off, int* __restrict__ bsum) {
    __shared__ int sh[1024];
    int gid = blockIdx.x * 1024 + threadIdx.x;
    int v = (gid < N_NODES) ? hist[gid] : 0;
    sh[threadIdx.x] = v;
    __syncthreads();
    for (int o = 1; o < 1024; o <<= 1) {
        int t = (threadIdx.x >= o) ? sh[threadIdx.x - o] : 0;
        __syncthreads();
        sh[threadIdx.x] += t;
        __syncthreads();
    }
    if (gid < N_NODES) off[gid] = sh[threadIdx.x] - v;
    if (threadIdx.x == 1023) bsum[blockIdx.x] = sh[1023];
}
__global__ void scan2_kernel(int* bsum) {
    if (threadIdx.x == 0 && blockIdx.x == 0) {
        int run = 0;
        for (int i = 0; i < SCAN_NB; i++) { int t = bsum[i]; bsum[i] = run; run += t; }
    }
}
__global__ void scan3_kernel(int* __restrict__ off, const int* __restrict__ bsum,
                             int* __restrict__ cursor) {
    int gid = blockIdx.x * blockDim.x + threadIdx.x;
    if (gid < N_NODES) {
        int v = off[gid] + bsum[gid >> 10];
        off[gid] = v;
        cursor[gid] = v;
    }
    if (gid == 0) off[N_NODES] = N_EDGES;
}
__global__ void fill_kernel(const void* __restrict__ ei,
                            int* __restrict__ cursor, int* __restrict__ csr) {
    int e = blockIdx.x * blockDim.x + threadIdx.x;
    if (e >= N_EDGES) return;
    int s = load_idx(ei, e);
    int d = load_idx(ei, N_EDGES + e);
    csr[atomicAdd(&cursor[d], 1)] = s;
}

// ---- CSR mean aggregation: one warp per node, register fp32 accumulate ----
template<int D>
__global__ void agg_kernel(const __half* __restrict__ feat,
                           const int* __restrict__ off,
                           const int* __restrict__ csr,
                           __half* __restrict__ out) {
    int warp = (blockIdx.x * blockDim.x + threadIdx.x) >> 5;
    int lane = threadIdx.x & 31;
    if (warp >= N_NODES) return;
    const int beg = off[warp], end = off[warp + 1];
    constexpr int H  = D / 32;       // halves per lane
    constexpr int H2 = H / 2;        // half2 per lane

    float acc[H];
#pragma unroll
    for (int i = 0; i < H; i++) acc[i] = 0.f;

    int j = beg;
    for (; j + 1 < end; j += 2) {
        int s0 = csr[j], s1 = csr[j + 1];
        uint32_t v0[H2], v1[H2];
        if (H2 == 2) {
            uint2 t0 = *(const uint2*)(feat + (size_t)s0 * D + lane * H);
            uint2 t1 = *(const uint2*)(feat + (size_t)s1 * D + lane * H);
            v0[0] = t0.x; v0[1] = t0.y; v1[0] = t1.x; v1[1] = t1.y;
        } else {
            uint4 t0 = *(const uint4*)(feat + (size_t)s0 * D + lane * H);
            uint4 t1 = *(const uint4*)(feat + (size_t)s1 * D + lane * H);
            v0[0] = t0.x; v0[1] = t0.y; v0[2] = t0.z; v0[3] = t0.w;
            v1[0] = t1.x; v1[1] = t1.y; v1[2] = t1.z; v1[3] = t1.w;
        }
#pragma unroll
        for (int i = 0; i < H2; i++) {
            float2 f0 = __half22float2(*(const __half2*)&v0[i]);
            float2 f1 = __half22float2(*(const __half2*)&v1[i]);
            acc[2*i]   += f0.x + f1.x;
            acc[2*i+1] += f0.y + f1.y;
        }
    }
    if (j < end) {
        int s0 = csr[j];
        uint32_t v0[H2];
        if (H2 == 2) {
            uint2 t0 = *(const uint2*)(feat + (size_t)s0 * D + lane * H);
            v0[0] = t0.x; v0[1] = t0.y;
        } else {
            uint4 t0 = *(const uint4*)(feat + (size_t)s0 * D + lane * H);
            v0[0] = t0.x; v0[1] = t0.y; v0[2] = t0.z; v0[3] = t0.w;
        }
#pragma unroll
        for (int i = 0; i < H2; i++) {
            float2 f0 = __half22float2(*(const __half2*)&v0[i]);
            acc[2*i] += f0.x; acc[2*i+1] += f0.y;
        }
    }

    float inv = 1.f / fmaxf((float)(end - beg), 1.f);
    uint32_t w[H2];
#pragma unroll
    for (int i = 0; i < H2; i++) {
        __half2 r = __floats2half2_rn(acc[2*i] * inv, acc[2*i+1] * inv);
        w[i] = *(uint32_t*)&r;
    }
    __half* op = out + (size_t)warp * D + lane * H;
    if (H2 == 2) *(uint2*)op = make_uint2(w[0], w[1]);
    else         *(uint4*)op = make_uint4(w[0], w[1], w[2], w[3]);
}

// ---- Prep: x -> fp16, weights -> fp16 hi/lo ----
#define N4_X   (N_NODES * D_IN / 4)
#define N4_W1  (D_HID * D_IN / 4)
#define N4_W2  (D_OUT * D_HID / 4)
__device__ __forceinline__ uint2 to_h4(float4 v) {
    __half2 p0 = __floats2half2_rn(v.x, v.y);
    __half2 p1 = __floats2half2_rn(v.z, v.w);
    return make_uint2(*(uint32_t*)&p0, *(uint32_t*)&p1);
}
__device__ __forceinline__ void split_h4(float4 v, uint2& hi, uint2& lo) {
    __half h0 = __float2half_rn(v.x), h1 = __float2half_rn(v.y);
    __half h2 = __float2half_rn(v.z), h3 = __float2half_rn(v.w);
    __half l0 = __float2half_rn(v.x - __half2float(h0));
    __half l1 = __float2half_rn(v.y - __half2float(h1));
    __half l2 = __float2half_rn(v.z - __half2float(h2));
    __half l3 = __float2half_rn(v.w - __half2float(h3));
    __half2 ph0 = __halves2half2(h0, h1), ph1 = __halves2half2(h2, h3);
    __half2 pl0 = __halves2half2(l0, l1), pl1 = __halves2half2(l2, l3);
    hi = make_uint2(*(uint32_t*)&ph0, *(uint32_t*)&ph1);
    lo = make_uint2(*(uint32_t*)&pl0, *(uint32_t*)&pl1);
}
__global__ void prep_kernel(const float* x,
                            const float* wl1, const float* wr1,
                            const float* wl2, const float* wr2,
                            __half* x16,
                            __half* wl1h, __half* wl1l, __half* wr1h, __half* wr1l,
                            __half* wl2h, __half* wl2l, __half* wr2h, __half* wr2l) {
    int i = blockIdx.x * blockDim.x + threadIdx.x;
    if (i < N4_X) {
        ((uint2*)x16)[i] = to_h4(((const float4*)x)[i]);
        return;
    }
    int j = i - N4_X;
    const float* src; __half *ph, *pl;
    if (j < N4_W1)                 { src = wl1; ph = wl1h; pl = wl1l; }
    else if (j < 2 * N4_W1)        { j -= N4_W1;   src = wr1; ph = wr1h; pl = wr1l; }
    else if (j < 2*N4_W1 + N4_W2)  { j -= 2*N4_W1; src = wl2; ph = wl2h; pl = wl2l; }
    else if (j < 2*N4_W1 + 2*N4_W2){ j -= 2*N4_W1 + N4_W2; src = wr2; ph = wr2h; pl = wr2l; }
    else return;
    uint2 hi, lo;
    split_h4(((const float4*)src)[j], hi, lo);
    ((uint2*)ph)[j] = hi;
    ((uint2*)pl)[j] = lo;
}
#define PREP_TOTAL (N4_X + 2 * N4_W1 + 2 * N4_W2)

// ---- fp16 2-pass fused GEMM (unchanged from round 6) ----
#define PITCH 144
#define TILE_BYTES (128 * PITCH)
#define STAGE_BYTES (3 * TILE_BYTES)
#define GEMM_SMEM (2 * STAGE_BYTES)

template<int K1, bool F16OUT>
__global__ __launch_bounds__(256, 2)
void gemm2p_kernel(const __half* __restrict__ A1, const __half* __restrict__ A2,
                   const __half* __restrict__ B1h, const __half* __restrict__ B1l,
                   const __half* __restrict__ B2h, const __half* __restrict__ B2l,
                   const float* __restrict__ bias, float* __restrict__ C,
                   __half* __restrict__ H, int M) {
    extern __shared__ char smem[];
    constexpr int NCH = K1 / 64;
    constexpr int CT  = 2 * NCH;

    const uint32_t smem_base = smem_to_u32(smem);
    const int tid = threadIdx.x;
    const int wid = tid >> 5, lane = tid & 31;
    const int wm = wid & 3, wn = wid >> 2;
    const int m0  = blockIdx.x * 128;
    const int bn0 = blockIdx.y * 128;

    float acc[2][8][4];
#pragma unroll
    for (int i = 0; i < 2; i++)
#pragma unroll
        for (int j = 0; j < 8; j++)
#pragma unroll
            for (int r = 0; r < 4; r++) acc[i][j][r] = 0.f;

    auto issue = [&](int c, int stg) {
        const int mtx = c / NCH;
        const int k0 = (c % NCH) * 64;
        const __half* Ap = mtx ? A2 : A1;
        const __half* Bh = mtx ? B2h : B1h;
        const __half* Bl = mtx ? B2l : B1l;
        const uint32_t s0 = smem_base + stg * STAGE_BYTES;
#pragma unroll
        for (int it = 0; it < 4; it++) {
            int idx = tid + it * 256;
            int row = idx >> 3, ch = idx & 7;
            int gm = m0 + row;
            cp_async16(s0 + row * PITCH + ch * 16,
                       Ap + (size_t)gm * K1 + k0 + ch * 8, gm < M);
            cp_async16(s0 + TILE_BYTES + row * PITCH + ch * 16,
                       Bh + (size_t)(bn0 + row) * K1 + k0 + ch * 8, true);
            cp_async16(s0 + 2 * TILE_BYTES + row * PITCH + ch * 16,
                       Bl + (size_t)(bn0 + row) * K1 + k0 + ch * 8, true);
        }
        cp_commit();
    };

    issue(0, 0);

    const int arow = wm * 32 + (lane & 15);
    const int brow = wn * 64 + (lane & 15);
    const int chi  = lane >> 4;

    for (int c = 0; c < CT; c++) {
        const int s = c & 1;
        if (c + 1 < CT) issue(c + 1, s ^ 1);

        if (c + 1 < CT) asm volatile("cp.async.wait_group 1;" ::: "memory");
        else            asm volatile("cp.async.wait_group 0;" ::: "memory");
        __syncthreads();

        const uint32_t sa = smem_base + s * STAGE_BYTES;
#pragma unroll
        for (int kk = 0; kk < 4; kk++) {
            uint32_t a[2][4];
#pragma unroll
            for (int am = 0; am < 2; am++)
                ldsm_x4(a[am], sa + (uint32_t)(arow + am * 16) * PITCH
                                  + (uint32_t)(kk * 2 + chi) * 16);
#pragma unroll
            for (int p = 0; p < 2; p++) {
                const uint32_t sb = sa + (1 + p) * TILE_BYTES;
                uint32_t b[4][4];
#pragma unroll
                for (int bi = 0; bi < 4; bi++)
                    ldsm_x4(b[bi], sb + (uint32_t)(brow + bi * 16) * PITCH
                                      + (uint32_t)(kk * 2 + chi) * 16);
#pragma unroll
                for (int am = 0; am < 2; am++)
#pragma unroll
                    for (int bi = 0; bi < 4; bi++) {
                        mma16816(acc[am][2 * bi + 0], a[am], b[bi][0], b[bi][2]);
                        mma16816(acc[am][2 * bi + 1], a[am], b[bi][1], b[bi][3]);
                    }
            }
        }
        __syncthreads();
    }

#pragma unroll
    for (int am = 0; am < 2; am++) {
        int gm = m0 + wm * 32 + am * 16 + (lane >> 2);
#pragma unroll
        for (int bi = 0; bi < 8; bi++) {
            int gn = bn0 + wn * 64 + bi * 8 + (lane & 3) * 2;
            float bz0 = bias[gn], bz1 = bias[gn + 1];
#pragma unroll
            for (int half = 0; half < 2; half++) {
                int r = gm + half * 8;
                if (r >= M) continue;
                float v0 = fmaxf(acc[am][bi][2 * half + 0] + bz0, 0.f);
                float v1 = fmaxf(acc[am][bi][2 * half + 1] + bz1, 0.f);
                if (F16OUT) {
                    __half2 p = __floats2half2_rn(v0, v1);
                    *(uint32_t*)(H + (size_t)r * 256 + gn) = *(uint32_t*)&p;
                } else {
                    *(float2*)(C + (size_t)r * 256 + gn) = make_float2(v0, v1);
                }
            }
        }
    }
}

// ---- Launch ----
extern "C" void kernel_launch(void* const* d_in, const int* in_sizes, int n_in,
                              void* d_out, int out_size) {
    const float* x    = (const float*)d_in[0];
    const void*  ei   = d_in[1];
    const float* w_l1 = (const float*)d_in[2];
    const float* b_l1 = (const float*)d_in[3];
    const float* w_r1 = (const float*)d_in[4];
    const float* w_l2 = (const float*)d_in[5];
    const float* b_l2 = (const float*)d_in[6];
    const float* w_r2 = (const float*)d_in[7];
    float* out = (float*)d_out;

    int *hist, *off, *cursor, *bsum, *csr;
    cudaGetSymbolAddress((void**)&hist,   g_hist);
    cudaGetSymbolAddress((void**)&off,    g_off);
    cudaGetSymbolAddress((void**)&cursor, g_cursor);
    cudaGetSymbolAddress((void**)&bsum,   g_bsum);
    cudaGetSymbolAddress((void**)&csr,    g_csr);
    __half *x16, *a116, *h16, *a216;
    __half *wl1h, *wl1l, *wr1h, *wr1l, *wl2h, *wl2l, *wr2h, *wr2l;
    cudaGetSymbolAddress((void**)&x16,  g_x16);
    cudaGetSymbolAddress((void**)&a116, g_a116);
    cudaGetSymbolAddress((void**)&h16,  g_h16);
    cudaGetSymbolAddress((void**)&a216, g_a216);
    cudaGetSymbolAddress((void**)&wl1h, g_wl1h); cudaGetSymbolAddress((void**)&wl1l, g_wl1l);
    cudaGetSymbolAddress((void**)&wr1h, g_wr1h); cudaGetSymbolAddress((void**)&wr1l, g_wr1l);
    cudaGetSymbolAddress((void**)&wl2h, g_wl2h); cudaGetSymbolAddress((void**)&wl2l, g_wl2l);
    cudaGetSymbolAddress((void**)&wr2h, g_wr2h); cudaGetSymbolAddress((void**)&wr2l, g_wr2l);

    cudaFuncSetAttribute(gemm2p_kernel<D_IN,  true >,
                         cudaFuncAttributeMaxDynamicSharedMemorySize, GEMM_SMEM);
    cudaFuncSetAttribute(gemm2p_kernel<D_HID, false>,
                         cudaFuncAttributeMaxDynamicSharedMemorySize, GEMM_SMEM);

    // Prep + CSR build
    detect_idx_kernel<<<1, 256>>>((const long long*)ei);
    zero_hist_kernel<<<(N_NODES + 255) / 256, 256>>>(hist);
    prep_kernel<<<(PREP_TOTAL + 255) / 256, 256>>>(
        x, w_l1, w_r1, w_l2, w_r2, x16,
        wl1h, wl1l, wr1h, wr1l, wl2h, wl2l, wr2h, wr2l);
    hist_kernel<<<(N_EDGES + 255) / 256, 256>>>(ei, hist);
    scan1_kernel<<<SCAN_NB, 1024>>>(hist, off, bsum);
    scan2_kernel<<<1, 32>>>(bsum);
    scan3_kernel<<<(N_NODES + 255) / 256, 256>>>(off, bsum, cursor);
    fill_kernel<<<(N_EDGES + 255) / 256, 256>>>(ei, cursor, csr);

    const dim3 gemm_grid((N_NODES + 127) / 128, 2);
    const int agg_blocks = (N_NODES * 32 + 255) / 256;

    // Layer 1
    agg_kernel<D_IN><<<agg_blocks, 256>>>(x16, off, csr, a116);
    gemm2p_kernel<D_IN, true><<<gemm_grid, 256, GEMM_SMEM>>>(
        a116, x16, wl1h, wl1l, wr1h, wr1l, b_l1, nullptr, h16, N_NODES);

    // Layer 2
    agg_kernel<D_HID><<<agg_blocks, 256>>>(h16, off, csr, a216);
    gemm2p_kernel<D_HID, false><<<gemm_grid, 256, GEMM_SMEM>>>(
        a216, h16, wl2h, wl2l, wr2h, wr2l, b_l2, out, nullptr, N_NODES);
}

// round 8
// speedup vs baseline: 4.8587x; 1.2859x over previous
#include <cuda_runtime.h>
#include <cuda_fp16.h>
#include <cstdint>

#define N_NODES 50000
#define N_EDGES 800000
#define D_IN    128
#define D_HID   256
#define D_OUT   256

__device__ int g_is64;
__device__ int g_hist[N_NODES];
__device__ int g_off[N_NODES + 1];
__device__ int g_cursor[N_NODES];
__device__ int g_bsum[64];
__device__ int g_csr[N_EDGES];

#define F16ARR __device__ __align__(16) __half
F16ARR g_x16 [(size_t)N_NODES * D_IN];
F16ARR g_a116[(size_t)N_NODES * D_IN];
F16ARR g_h16 [(size_t)N_NODES * D_HID];
F16ARR g_a216[(size_t)N_NODES * D_HID];
F16ARR g_wl1[D_HID * D_IN];
F16ARR g_wr1[D_HID * D_IN];
F16ARR g_wl2[D_OUT * D_HID];
F16ARR g_wr2[D_OUT * D_HID];

__device__ __forceinline__ uint32_t smem_to_u32(const void* p) {
    uint32_t a;
    asm("{ .reg .u64 t; cvta.to.shared.u64 t, %1; cvt.u32.u64 %0, t; }" : "=r"(a) : "l"(p));
    return a;
}
__device__ __forceinline__ void cp_async16(uint32_t dst, const void* src, bool valid) {
    int sz = valid ? 16 : 0;
    asm volatile("cp.async.cg.shared.global [%0], [%1], 16, %2;"
                 :: "r"(dst), "l"(src), "r"(sz) : "memory");
}
__device__ __forceinline__ void cp_commit() {
    asm volatile("cp.async.commit_group;" ::: "memory");
}
__device__ __forceinline__ void ldsm_x4(uint32_t* r, uint32_t addr) {
    asm volatile("ldmatrix.sync.aligned.m8n8.x4.shared.b16 {%0,%1,%2,%3}, [%4];"
                 : "=r"(r[0]), "=r"(r[1]), "=r"(r[2]), "=r"(r[3]) : "r"(addr));
}
__device__ __forceinline__ void mma16816(float* d, const uint32_t* a,
                                         uint32_t b0, uint32_t b1) {
    asm volatile("mma.sync.aligned.m16n8k16.row.col.f32.f16.f16.f32 "
                 "{%0,%1,%2,%3}, {%4,%5,%6,%7}, {%8,%9}, {%0,%1,%2,%3};"
                 : "+f"(d[0]), "+f"(d[1]), "+f"(d[2]), "+f"(d[3])
                 : "r"(a[0]), "r"(a[1]), "r"(a[2]), "r"(a[3]), "r"(b0), "r"(b1));
}

__global__ void detect_idx_kernel(const long long* __restrict__ p) {
    __shared__ int bad;
    if (threadIdx.x == 0) bad = 0;
    __syncthreads();
    for (int i = threadIdx.x; i < 4096; i += blockDim.x) {
        long long v = p[i];
        if (v < 0 || v >= N_NODES) bad = 1;
    }
    __syncthreads();
    if (threadIdx.x == 0) g_is64 = bad ? 0 : 1;
}
__device__ __forceinline__ int load_idx(const void* base, int i) {
    if (g_is64) return (int)((const long long*)base)[i];
    return ((const int*)base)[i];
}

// ---- CSR build ----
__global__ void zero_hist_kernel(int* hist) {
    int i = blockIdx.x * blockDim.x + threadIdx.x;
    if (i < N_NODES) hist[i] = 0;
}
__global__ void hist_kernel(const void* __restrict__ ei, int* __restrict__ hist) {
    int e = blockIdx.x * blockDim.x + threadIdx.x;
    if (e >= N_EDGES) return;
    atomicAdd(&hist[load_idx(ei, N_EDGES + e)], 1);
}
#define SCAN_NB ((N_NODES + 1023) / 1024)   // 49
__global__ void scan1_kernel(const int* __restrict__ hist,
                             int* __restrict__ off, int* __restrict__ bsum) {
    __shared__ int sh[1024];
    int gid = blockIdx.x * 1024 + threadIdx.x;
    int v = (gid < N_NODES) ? hist[gid] : 0;
    sh[threadIdx.x] = v;
    __syncthreads();
    for (int o = 1; o < 1024; o <<= 1) {
        int t = (threadIdx.x >= o) ? sh[threadIdx.x - o] : 0;
        __syncthreads();
        sh[threadIdx.x] += t;
        __syncthreads();
    }
    if (gid < N_NODES) off[gid] = sh[threadIdx.x] - v;
    if (threadIdx.x == 1023) bsum[blockIdx.x] = sh[1023];
}
__global__ void scan2_kernel(int* bsum) {
    if (threadIdx.x == 0 && blockIdx.x == 0) {
        int run = 0;
        for (int i = 0; i < SCAN_NB; i++) { int t = bsum[i]; bsum[i] = run; run += t; }
    }
}
__global__ void scan3_kernel(int* __restrict__ off, const int* __restrict__ bsum,
                             int* __restrict__ cursor) {
    int gid = blockIdx.x * blockDim.x + threadIdx.x;
    if (gid < N_NODES) {
        int v = off[gid] + bsum[gid >> 10];
        off[gid] = v;
        cursor[gid] = v;
    }
    if (gid == 0) off[N_NODES] = N_EDGES;
}
__global__ void fill_kernel(const void* __restrict__ ei,
                            int* __restrict__ cursor, int* __restrict__ csr) {
    int e = blockIdx.x * blockDim.x + threadIdx.x;
    if (e >= N_EDGES) return;
    int s = load_idx(ei, e);
    int d = load_idx(ei, N_EDGES + e);
    csr[atomicAdd(&cursor[d], 1)] = s;
}

// ---- CSR mean aggregation: one warp per node, register fp32 accumulate ----
template<int D>
__global__ void agg_kernel(const __half* __restrict__ feat,
                           const int* __restrict__ off,
                           const int* __restrict__ csr,
                           __half* __restrict__ out) {
    int warp = (blockIdx.x * blockDim.x + threadIdx.x) >> 5;
    int lane = threadIdx.x & 31;
    if (warp >= N_NODES) return;
    const int beg = off[warp], end = off[warp + 1];
    constexpr int H  = D / 32;       // halves per lane
    constexpr int H2 = H / 2;        // half2 per lane

    float acc[H];
#pragma unroll
    for (int i = 0; i < H; i++) acc[i] = 0.f;

    int j = beg;
    for (; j + 1 < end; j += 2) {
        int s0 = csr[j], s1 = csr[j + 1];
        uint32_t v0[H2], v1[H2];
        if (H2 == 2) {
            uint2 t0 = *(const uint2*)(feat + (size_t)s0 * D + lane * H);
            uint2 t1 = *(const uint2*)(feat + (size_t)s1 * D + lane * H);
            v0[0] = t0.x; v0[1] = t0.y; v1[0] = t1.x; v1[1] = t1.y;
        } else {
            uint4 t0 = *(const uint4*)(feat + (size_t)s0 * D + lane * H);
            uint4 t1 = *(const uint4*)(feat + (size_t)s1 * D + lane * H);
            v0[0] = t0.x; v0[1] = t0.y; v0[2] = t0.z; v0[3] = t0.w;
            v1[0] = t1.x; v1[1] = t1.y; v1[2] = t1.z; v1[3] = t1.w;
        }
#pragma unroll
        for (int i = 0; i < H2; i++) {
            float2 f0 = __half22float2(*(const __half2*)&v0[i]);
            float2 f1 = __half22float2(*(const __half2*)&v1[i]);
            acc[2*i]   += f0.x + f1.x;
            acc[2*i+1] += f0.y + f1.y;
        }
    }
    if (j < end) {
        int s0 = csr[j];
        uint32_t v0[H2];
        if (H2 == 2) {
            uint2 t0 = *(const uint2*)(feat + (size_t)s0 * D + lane * H);
            v0[0] = t0.x; v0[1] = t0.y;
        } else {
            uint4 t0 = *(const uint4*)(feat + (size_t)s0 * D + lane * H);
            v0[0] = t0.x; v0[1] = t0.y; v0[2] = t0.z; v0[3] = t0.w;
        }
#pragma unroll
        for (int i = 0; i < H2; i++) {
            float2 f0 = __half22float2(*(const __half2*)&v0[i]);
            acc[2*i] += f0.x; acc[2*i+1] += f0.y;
        }
    }

    float inv = 1.f / fmaxf((float)(end - beg), 1.f);
    uint32_t w[H2];
#pragma unroll
    for (int i = 0; i < H2; i++) {
        __half2 r = __floats2half2_rn(acc[2*i] * inv, acc[2*i+1] * inv);
        w[i] = *(uint32_t*)&r;
    }
    __half* op = out + (size_t)warp * D + lane * H;
    if (H2 == 2) *(uint2*)op = make_uint2(w[0], w[1]);
    else         *(uint4*)op = make_uint4(w[0], w[1], w[2], w[3]);
}

// ---- Prep: x and all weights -> fp16 (single pass, no hi/lo split) ----
#define N4_X   (N_NODES * D_IN / 4)
#define N4_W1  (D_HID * D_IN / 4)
#define N4_W2  (D_OUT * D_HID / 4)
__device__ __forceinline__ uint2 to_h4(float4 v) {
    __half2 p0 = __floats2half2_rn(v.x, v.y);
    __half2 p1 = __floats2half2_rn(v.z, v.w);
    return make_uint2(*(uint32_t*)&p0, *(uint32_t*)&p1);
}
__global__ void prep_kernel(const float* x,
                            const float* wl1, const float* wr1,
                            const float* wl2, const float* wr2,
                            __half* x16, __half* wl1h, __half* wr1h,
                            __half* wl2h, __half* wr2h) {
    int i = blockIdx.x * blockDim.x + threadIdx.x;
    const float* src; __half* dst; int j = i;
    if (i < N4_X)                        { src = x;   dst = x16; }
    else if ((j -= N4_X)      < N4_W1)   { src = wl1; dst = wl1h; }
    else if ((j -= N4_W1)     < N4_W1)   { src = wr1; dst = wr1h; }
    else if ((j -= N4_W1)     < N4_W2)   { src = wl2; dst = wl2h; }
    else if ((j -= N4_W2)     < N4_W2)   { src = wr2; dst = wr2h; }
    else return;
    ((uint2*)dst)[j] = to_h4(((const float4*)src)[j]);
}
#define PREP_TOTAL (N4_X + 2 * N4_W1 + 2 * N4_W2)

// ---- Single-pass fp16 fused GEMM, 3-stage cp.async ring:
//   C[M,256] = relu( A1@B1^T + A2@B2^T + bias )
// CTA tile 128x128, 8 warps (4x2), warp tile 32x64, K chunk 64.
// Stage = A tile + B tile (pitch 144, conflict-free ldmatrix).
// ----
#define PITCH 144
#define TILE_BYTES (128 * PITCH)              // 18432
#define STAGE_BYTES (2 * TILE_BYTES)          // 36864
#define GEMM_SMEM (3 * STAGE_BYTES)           // 110592

template<int K1, bool F16OUT>
__global__ __launch_bounds__(256, 2)
void gemm1p_kernel(const __half* __restrict__ A1, const __half* __restrict__ A2,
                   const __half* __restrict__ B1, const __half* __restrict__ B2,
                   const float* __restrict__ bias, float* __restrict__ C,
                   __half* __restrict__ H, int M) {
    extern __shared__ char smem[];
    constexpr int NCH = K1 / 64;        // chunks per matrix
    constexpr int CT  = 2 * NCH;        // total chunks

    const uint32_t smem_base = smem_to_u32(smem);
    const int tid = threadIdx.x;
    const int wid = tid >> 5, lane = tid & 31;
    const int wm = wid & 3, wn = wid >> 2;
    const int m0  = blockIdx.x * 128;
    const int bn0 = blockIdx.y * 128;

    float acc[2][8][4];
#pragma unroll
    for (int i = 0; i < 2; i++)
#pragma unroll
        for (int j = 0; j < 8; j++)
#pragma unroll
            for (int r = 0; r < 4; r++) acc[i][j][r] = 0.f;

    auto issue = [&](int c, int stg) {
        const int mtx = c / NCH;
        const int k0 = (c % NCH) * 64;
        const __half* Ap = mtx ? A2 : A1;
        const __half* Bp = mtx ? B2 : B1;
        const uint32_t s0 = smem_base + stg * STAGE_BYTES;
#pragma unroll
        for (int it = 0; it < 4; it++) {
            int idx = tid + it * 256;
            int row = idx >> 3, ch = idx & 7;
            int gm = m0 + row;
            cp_async16(s0 + row * PITCH + ch * 16,
                       Ap + (size_t)gm * K1 + k0 + ch * 8, gm < M);
            cp_async16(s0 + TILE_BYTES + row * PITCH + ch * 16,
                       Bp + (size_t)(bn0 + row) * K1 + k0 + ch * 8, true);
        }
        cp_commit();
    };

    issue(0, 0);
    if (CT > 1) issue(1, 1);

    const int arow = wm * 32 + (lane & 15);
    const int brow = wn * 64 + (lane & 15);
    const int chi  = lane >> 4;

    for (int c = 0; c < CT; c++) {
        const int s = c % 3;
        if (c + 2 < CT) issue(c + 2, (c + 2) % 3);

        if (c + 2 < CT)      asm volatile("cp.async.wait_group 2;" ::: "memory");
        else if (c + 1 < CT) asm volatile("cp.async.wait_group 1;" ::: "memory");
        else                 asm volatile("cp.async.wait_group 0;" ::: "memory");
        __syncthreads();

        const uint32_t sa = smem_base + s * STAGE_BYTES;
        const uint32_t sb = sa + TILE_BYTES;
#pragma unroll
        for (int kk = 0; kk < 4; kk++) {
            uint32_t a[2][4], b[4][4];
#pragma unroll
            for (int am = 0; am < 2; am++)
                ldsm_x4(a[am], sa + (uint32_t)(arow + am * 16) * PITCH
                                  + (uint32_t)(kk * 2 + chi) * 16);
#pragma unroll
            for (int bi = 0; bi < 4; bi++)
                ldsm_x4(b[bi], sb + (uint32_t)(brow + bi * 16) * PITCH
                                  + (uint32_t)(kk * 2 + chi) * 16);
#pragma unroll
            for (int am = 0; am < 2; am++)
#pragma unroll
                for (int bi = 0; bi < 4; bi++) {
                    mma16816(acc[am][2 * bi + 0], a[am], b[bi][0], b[bi][2]);
                    mma16816(acc[am][2 * bi + 1], a[am], b[bi][1], b[bi][3]);
                }
        }
        __syncthreads();
    }

    // ---- epilogue: bias + relu; fp16 H or fp32 C ----
#pragma unroll
    for (int am = 0; am < 2; am++) {
        int gm = m0 + wm * 32 + am * 16 + (lane >> 2);
#pragma unroll
        for (int bi = 0; bi < 8; bi++) {
            int gn = bn0 + wn * 64 + bi * 8 + (lane & 3) * 2;
            float bz0 = bias[gn], bz1 = bias[gn + 1];
#pragma unroll
            for (int half = 0; half < 2; half++) {
                int r = gm + half * 8;
                if (r >= M) continue;
                float v0 = fmaxf(acc[am][bi][2 * half + 0] + bz0, 0.f);
                float v1 = fmaxf(acc[am][bi][2 * half + 1] + bz1, 0.f);
                if (F16OUT) {
                    __half2 p = __floats2half2_rn(v0, v1);
                    *(uint32_t*)(H + (size_t)r * 256 + gn) = *(uint32_t*)&p;
                } else {
                    *(float2*)(C + (size_t)r * 256 + gn) = make_float2(v0, v1);
                }
            }
        }
    }
}

// ---- Launch ----
extern "C" void kernel_launch(void* const* d_in, const int* in_sizes, int n_in,
                              void* d_out, int out_size) {
    const float* x    = (const float*)d_in[0];
    const void*  ei   = d_in[1];
    const float* w_l1 = (const float*)d_in[2];
    const float* b_l1 = (const float*)d_in[3];
    const float* w_r1 = (const float*)d_in[4];
    const float* w_l2 = (const float*)d_in[5];
    const float* b_l2 = (const float*)d_in[6];
    const float* w_r2 = (const float*)d_in[7];
    float* out = (float*)d_out;

    int *hist, *off, *cursor, *bsum, *csr;
    cudaGetSymbolAddress((void**)&hist,   g_hist);
    cudaGetSymbolAddress((void**)&off,    g_off);
    cudaGetSymbolAddress((void**)&cursor, g_cursor);
    cudaGetSymbolAddress((void**)&bsum,   g_bsum);
    cudaGetSymbolAddress((void**)&csr,    g_csr);
    __half *x16, *a116, *h16, *a216, *wl1, *wr1, *wl2, *wr2;
    cudaGetSymbolAddress((void**)&x16,  g_x16);
    cudaGetSymbolAddress((void**)&a116, g_a116);
    cudaGetSymbolAddress((void**)&h16,  g_h16);
    cudaGetSymbolAddress((void**)&a216, g_a216);
    cudaGetSymbolAddress((void**)&wl1,  g_wl1);
    cudaGetSymbolAddress((void**)&wr1,  g_wr1);
    cudaGetSymbolAddress((void**)&wl2,  g_wl2);
    cudaGetSymbolAddress((void**)&wr2,  g_wr2);

    cudaFuncSetAttribute(gemm1p_kernel<D_IN,  true >,
                         cudaFuncAttributeMaxDynamicSharedMemorySize, GEMM_SMEM);
    cudaFuncSetAttribute(gemm1p_kernel<D_HID, false>,
                         cudaFuncAttributeMaxDynamicSharedMemorySize, GEMM_SMEM);

    // Prep + CSR build
    detect_idx_kernel<<<1, 256>>>((const long long*)ei);
    zero_hist_kernel<<<(N_NODES + 255) / 256, 256>>>(hist);
    prep_kernel<<<(PREP_TOTAL + 255) / 256, 256>>>(
        x, w_l1, w_r1, w_l2, w_r2, x16, wl1, wr1, wl2, wr2);
    hist_kernel<<<(N_EDGES + 255) / 256, 256>>>(ei, hist);
    scan1_kernel<<<SCAN_NB, 1024>>>(hist, off, bsum);
    scan2_kernel<<<1, 32>>>(bsum);
    scan3_kernel<<<(N_NODES + 255) / 256, 256>>>(off, bsum, cursor);
    fill_kernel<<<(N_EDGES + 255) / 256, 256>>>(ei, cursor, csr);

    const dim3 gemm_grid((N_NODES + 127) / 128, 2);
    const int agg_blocks = (N_NODES * 32 + 255) / 256;

    // Layer 1
    agg_kernel<D_IN><<<agg_blocks, 256>>>(x16, off, csr, a116);
    gemm1p_kernel<D_IN, true><<<gemm_grid, 256, GEMM_SMEM>>>(
        a116, x16, wl1, wr1, b_l1, nullptr, h16, N_NODES);

    // Layer 2
    agg_kernel<D_HID><<<agg_blocks, 256>>>(h16, off, csr, a216);
    gemm1p_kernel<D_HID, false><<<gemm_grid, 256, GEMM_SMEM>>>(
        a216, h16, wl2, wr2, b_l2, out, nullptr, N_NODES);
}